// round 13
// baseline (speedup 1.0000x reference)
#include <cuda_runtime.h>

// out[i] = sum_j relu(adj[i,j] * Linv[i,j]) * W[j] + b
// N = 8192. Inputs: d_in[0]=x_e (unused), d_in[1]=Linv, d_in[2]=adjacency,
// d_in[3]=W (N floats), d_in[4]=b (1 float). Output: N floats ([N,1]).
//
// Stage 1: 16384 CTAs, one per half-row. Publishes partial via __stcg and a
// fire-and-forget red.release (no return value -> no critical-path stall).
// Stage 2: combiner launched with PDL (programmatic stream serialization);
// stage 1 signals launch_dependents at CTA start, so the combiner overlaps
// stage 1's tail, spinning per-row on flags with acquire loads.
// Deterministic: combine is always p0 + p1 + b; combiner resets flags.

#define N_DIM 8192
#define THREADS 256
#define HALF_F4 (N_DIM / 4 / 2)   // 1024 float4 per half-row

__device__ float g_partials[2 * N_DIM];
__device__ int   g_flags[N_DIM];          // zero-init at load; combiner resets

__global__ __launch_bounds__(THREADS, 8)
void dist2cycle_halfrow_red_kernel(const float4* __restrict__ Linv,
                                   const float4* __restrict__ adj,
                                   const float4* __restrict__ W4) {
    // Allow the dependent (combiner) grid to launch as early as possible.
    if (threadIdx.x == 0)
        asm volatile("griddepcontrol.launch_dependents;");

    const int row  = blockIdx.x >> 1;
    const int half = blockIdx.x & 1;

    const size_t base = (size_t)row * (N_DIM / 4) + (size_t)half * HALF_F4;
    const float4* __restrict__ L = Linv + base;
    const float4* __restrict__ A = adj  + base;
    const float4* __restrict__ W = W4 + (size_t)half * HALF_F4;

    float acc = 0.0f;

    // 1024 float4 over 256 threads -> 4 iterations.
    #pragma unroll 4
    for (int j = threadIdx.x; j < HALF_F4; j += THREADS) {
        float4 l = __ldcs(&L[j]);
        float4 a = __ldcs(&A[j]);
        float4 w = __ldg(&W[j]);
        acc = fmaf(fmaxf(a.x * l.x, 0.0f), w.x, acc);
        acc = fmaf(fmaxf(a.y * l.y, 0.0f), w.y, acc);
        acc = fmaf(fmaxf(a.z * l.z, 0.0f), w.z, acc);
        acc = fmaf(fmaxf(a.w * l.w, 0.0f), w.w, acc);
    }

    // Warp reduce
    #pragma unroll
    for (int off = 16; off > 0; off >>= 1)
        acc += __shfl_xor_sync(0xFFFFFFFFu, acc, off);

    // Block reduce across 8 warps
    __shared__ float warp_sums[THREADS / 32];
    const int lane = threadIdx.x & 31;
    const int wid  = threadIdx.x >> 5;
    if (lane == 0) warp_sums[wid] = acc;
    __syncthreads();

    if (wid == 0) {
        float v = (lane < THREADS / 32) ? warp_sums[lane] : 0.0f;
        #pragma unroll
        for (int off = 4; off > 0; off >>= 1)
            v += __shfl_xor_sync(0xFFFFFFFFu, v, off);

        if (lane == 0) {
            __stcg(&g_partials[2 * row + half], v);
            // Fire-and-forget release reduction: orders the partial store
            // before the flag increment, returns nothing -> no stall.
            asm volatile("red.release.gpu.global.add.s32 [%0], 1;"
                         :: "l"(&g_flags[row]) : "memory");
        }
    }
}

__global__ __launch_bounds__(128)
void dist2cycle_pdl_combine_kernel(const float* __restrict__ bptr,
                                   float* __restrict__ out) {
    const int i = blockIdx.x * blockDim.x + threadIdx.x;
    const float b = __ldg(bptr);

    // Spin until both halves of row i have published (acquire pairs with
    // stage 1's red.release). Backoff keeps issue-slot theft negligible.
    int f;
    for (;;) {
        asm volatile("ld.acquire.gpu.global.s32 %0, [%1];"
                     : "=r"(f) : "l"(&g_flags[i]));
        if (f >= 2) break;
        __nanosleep(200);
    }

    float p0 = __ldcg(&g_partials[2 * i + 0]);
    float p1 = __ldcg(&g_partials[2 * i + 1]);
    out[i] = p0 + p1 + b;
    g_flags[i] = 0;   // reset for next graph replay (launch boundary orders it)
}

extern "C" void kernel_launch(void* const* d_in, const int* in_sizes, int n_in,
                              void* d_out, int out_size) {
    // metadata order: x_e, Linv, adjacency, W, b
    const float4* Linv = (const float4*)d_in[1];
    const float4* adj  = (const float4*)d_in[2];
    const float4* W4   = (const float4*)d_in[3];
    const float*  b    = (const float*)d_in[4];
    float* out = (float*)d_out;

    // Primary: half-row reduction.
    dist2cycle_halfrow_red_kernel<<<2 * N_DIM, THREADS>>>(Linv, adj, W4);

    // Secondary: PDL launch — may start while primary's tail is draining.
    cudaLaunchConfig_t cfg = {};
    cfg.gridDim  = dim3(N_DIM / 128, 1, 1);
    cfg.blockDim = dim3(128, 1, 1);
    cfg.dynamicSmemBytes = 0;
    cfg.stream = 0;
    cudaLaunchAttribute attr[1];
    attr[0].id = cudaLaunchAttributeProgrammaticStreamSerialization;
    attr[0].val.programmaticStreamSerializationAllowed = 1;
    cfg.attrs = attr;
    cfg.numAttrs = 1;
    cudaLaunchKernelEx(&cfg, dist2cycle_pdl_combine_kernel, b, out);
}